// round 15
// baseline (speedup 1.0000x reference)
#include <cuda_runtime.h>
#include <cuda_fp16.h>
#include <math.h>
#include <stddef.h>
#include <stdint.h>

#define BATCH 8
#define NT 1024
#define TD 128
#define HID 512
#define NH 8
#define HD 64
#define LOG2E 1.4426950408889634f

// ---------------- helpers ----------------
__device__ __forceinline__ float tf32r(float x){
    uint32_t u; asm("cvt.rna.tf32.f32 %0, %1;" : "=r"(u) : "f"(x));
    return __uint_as_float(u);
}
__device__ __forceinline__ void mma_tf32(float* c,
    uint32_t a0, uint32_t a1, uint32_t a2, uint32_t a3,
    uint32_t b0, uint32_t b1){
    asm("mma.sync.aligned.m16n8k8.row.col.f32.tf32.tf32.f32 "
        "{%0,%1,%2,%3}, {%4,%5,%6,%7}, {%8,%9}, {%0,%1,%2,%3};"
        : "+f"(c[0]), "+f"(c[1]), "+f"(c[2]), "+f"(c[3])
        : "r"(a0), "r"(a1), "r"(a2), "r"(a3), "r"(b0), "r"(b1));
}
__device__ __forceinline__ void mma_f16(float* c,
    uint32_t a0, uint32_t a1, uint32_t a2, uint32_t a3,
    uint32_t b0, uint32_t b1){
    asm("mma.sync.aligned.m16n8k16.row.col.f32.f16.f16.f32 "
        "{%0,%1,%2,%3}, {%4,%5,%6,%7}, {%8,%9}, {%0,%1,%2,%3};"
        : "+f"(c[0]), "+f"(c[1]), "+f"(c[2]), "+f"(c[3])
        : "r"(a0), "r"(a1), "r"(a2), "r"(a3), "r"(b0), "r"(b1));
}
__device__ __forceinline__ void ldm4t(uint32_t& r0, uint32_t& r1, uint32_t& r2, uint32_t& r3,
                                      uint32_t addr){
    asm volatile("ldmatrix.sync.aligned.m8n8.x4.trans.shared.b16 {%0,%1,%2,%3}, [%4];"
                 : "=r"(r0), "=r"(r1), "=r"(r2), "=r"(r3) : "r"(addr));
}
__device__ __forceinline__ uint32_t smem_u32(const void* p){
    uint32_t a;
    asm("{ .reg .u64 t; cvta.to.shared.u64 t, %1; cvt.u32.u64 %0, t; }" : "=r"(a) : "l"(p));
    return a;
}
__device__ __forceinline__ void cp16(uint32_t dst, const void* src){
    asm volatile("cp.async.cg.shared.global [%0], [%1], 16;" :: "r"(dst), "l"(src));
}
__device__ __forceinline__ void cp_commit(){
    asm volatile("cp.async.commit_group;" ::: "memory");
}
__device__ __forceinline__ void cp_wait0(){
    asm volatile("cp.async.wait_group 0;" ::: "memory");
}
__device__ __forceinline__ uint32_t f2h2(float lo, float hi){
    __half2 h = __floats2half2_rn(lo, hi);
    return *reinterpret_cast<uint32_t*>(&h);
}
// exp(0.1*t)*log2e for t in [0,1]: cubic Taylor in x=0.1t, rel err < 5e-6 (<< fp16 ulp)
__device__ __forceinline__ float expw(float t){
    float x = 0.1f * t;
    float p = fmaf(x, 0.16666667f, 0.5f);
    p = fmaf(x, p, 1.f);
    p = fmaf(x, p, 1.f);
    return p * LOG2E;
}

// ---------------- device scratch (static; no allocation) ----------------
__device__ unsigned g_tmax_u;                 // zero at load; atomicMax idempotent across replays
__device__ __half g_twm[BATCH * NT * NT];     // adj ? exp(0.1*t)*log2e : -1  (fp16)
__device__ float g_weff[TD * HID];            // struct_W^T @ W0cat (tf32-rounded)
__device__ float g_beff[HID];                 // struct_b @ W0cat
__device__ __half g_h[BATCH * NT * HID];      // h (fp16, rn)
__device__ float g_node[BATCH * NT * HID];    // GAT layer output (fp32)
__device__ float g_esrc[BATCH * NH * NT];
__device__ float g_edst[BATCH * NH * NT];

// ---------------- twm (fp16, polynomial exp) + tmax fused ----------------
__global__ void k_twm(const float4* __restrict__ tm, const int4* __restrict__ adj, int n4) {
    float m = 0.f;
    int stride = gridDim.x * blockDim.x;
    __half2* outp = reinterpret_cast<__half2*>(g_twm);
    for (int i = blockIdx.x * blockDim.x + threadIdx.x; i < n4; i += stride) {
        float4 t = tm[i];
        int4 a = adj[i];
        float4 o;
        o.x = a.x ? expw(t.x) : -1.f;
        o.y = a.y ? expw(t.y) : -1.f;
        o.z = a.z ? expw(t.z) : -1.f;
        o.w = a.w ? expw(t.w) : -1.f;
        outp[i * 2 + 0] = __floats2half2_rn(o.x, o.y);
        outp[i * 2 + 1] = __floats2half2_rn(o.z, o.w);
        m = fmaxf(m, fmaxf(fmaxf(t.x, t.y), fmaxf(t.z, t.w)));
    }
#pragma unroll
    for (int s = 16; s; s >>= 1) m = fmaxf(m, __shfl_xor_sync(0xffffffffu, m, s));
    __shared__ float sm[8];
    if ((threadIdx.x & 31) == 0) sm[threadIdx.x >> 5] = m;
    __syncthreads();
    if (threadIdx.x == 0) {
        for (int w = 1; w < 8; w++) m = fmaxf(m, sm[w]);
        atomicMax(&g_tmax_u, __float_as_uint(m));   // t >= 0: uint order == float order
    }
}

// ---------------- Weff = struct_W^T @ W0cat ; beff = struct_b @ W0cat ----------------
__global__ void k_weff(const float* __restrict__ sW, const float* __restrict__ sb,
                       const float* __restrict__ gW0,
                       float* __restrict__ weff, float* __restrict__ beff) {
    __shared__ float As[32][68];
    __shared__ float Bs[32][68];
    int t = threadIdx.x;
    int tx = t & 15, ty = t >> 4;
    int m0 = blockIdx.x * 64, n0 = blockIdx.y * 64;
    int hh = n0 >> 6;
    const float* B0 = gW0 + (size_t)hh * (HID * HD);
    float acc[4][4] = {};
    int bk = t >> 3, bnc = (t & 7) * 8;

    for (int kt = 0; kt < HID; kt += 32) {
        {
            const float* ap = sW + (size_t)(kt + bk) * TD + m0 + bnc;
            *reinterpret_cast<float4*>(&As[bk][bnc])     = *reinterpret_cast<const float4*>(ap);
            *reinterpret_cast<float4*>(&As[bk][bnc + 4]) = *reinterpret_cast<const float4*>(ap + 4);
            const float* bp = B0 + (size_t)(kt + bk) * HD + bnc;
            *reinterpret_cast<float4*>(&Bs[bk][bnc])     = *reinterpret_cast<const float4*>(bp);
            *reinterpret_cast<float4*>(&Bs[bk][bnc + 4]) = *reinterpret_cast<const float4*>(bp + 4);
        }
        __syncthreads();
#pragma unroll
        for (int k = 0; k < 32; k++) {
            float4 a4 = *reinterpret_cast<const float4*>(&As[k][ty * 4]);
            float4 b4 = *reinterpret_cast<const float4*>(&Bs[k][tx * 4]);
            acc[0][0] += a4.x * b4.x; acc[0][1] += a4.x * b4.y; acc[0][2] += a4.x * b4.z; acc[0][3] += a4.x * b4.w;
            acc[1][0] += a4.y * b4.x; acc[1][1] += a4.y * b4.y; acc[1][2] += a4.y * b4.z; acc[1][3] += a4.y * b4.w;
            acc[2][0] += a4.z * b4.x; acc[2][1] += a4.z * b4.y; acc[2][2] += a4.z * b4.z; acc[2][3] += a4.z * b4.w;
            acc[3][0] += a4.w * b4.x; acc[3][1] += a4.w * b4.y; acc[3][2] += a4.w * b4.z; acc[3][3] += a4.w * b4.w;
        }
        __syncthreads();
    }
#pragma unroll
    for (int ii = 0; ii < 4; ii++) {
        float4 o;   // tf32-round so gmma's HW truncation of B (layer 0) is exact
        o.x = tf32r(acc[ii][0]); o.y = tf32r(acc[ii][1]);
        o.z = tf32r(acc[ii][2]); o.w = tf32r(acc[ii][3]);
        *reinterpret_cast<float4*>(weff + (size_t)(m0 + ty * 4 + ii) * HID + n0 + tx * 4) = o;
    }
    if (blockIdx.x == 0 && t < 64) {
        float s = 0.f;
        for (int k = 0; k < HID; k++) s += sb[k] * B0[(size_t)k * HD + t];
        beff[n0 + t] = s;
    }
}

// ---------------- HMMA tf32 GEMM (M-block 128, N=64=one head) + fused se; h out fp16 ----------------
__global__ void __launch_bounds__(128) k_gmma(
    const float* __restrict__ A, const float* __restrict__ B,
    __half* __restrict__ C, const float* __restrict__ bias,
    int K, int bgat, const float* __restrict__ ga,
    float* __restrict__ esrc, float* __restrict__ edst) {
    __shared__ float Bs[2][32 * 68];

    int t = threadIdx.x;
    int wid = t >> 5, lid = t & 31;
    int g = lid >> 2, q = lid & 3;
    int m0 = blockIdx.x * 128;
    int hh = blockIdx.y;
    int n0 = hh * 64;

    const float* Bsrc = bgat ? (B + (size_t)hh * (HID * HD)) : (B + n0);
    int bstride = bgat ? HD : HID;

    int brow = t >> 2, bcol = (t & 3) * 16;
    uint32_t bs_base = smem_u32(Bs);
    uint32_t dst_off = (uint32_t)(brow * 68 + bcol) * 4u;

    {
        const float* src = Bsrc + (size_t)brow * bstride + bcol;
#pragma unroll
        for (int c = 0; c < 4; c++) cp16(bs_base + dst_off + c * 16u, src + c * 4);
        cp_commit();
    }

    int rbase = wid * 32 + g;
    const float* Aq = A + (size_t)(m0 + rbase) * K + 2 * q;

    float acc[2][8][4] = {};
    int ntiles = K / 32;

    for (int T = 0; T < ntiles; T++) {
        int k0 = T * 32;
        cp_wait0();
        __syncthreads();
        if (T + 1 < ntiles) {
            uint32_t buf = (uint32_t)((T + 1) & 1) * (32u * 68u * 4u);
            const float* src = Bsrc + (size_t)(k0 + 32 + brow) * bstride + bcol;
#pragma unroll
            for (int c = 0; c < 4; c++) cp16(bs_base + buf + dst_off + c * 16u, src + c * 4);
            cp_commit();
        }
        const float* bs = Bs[T & 1];
#pragma unroll
        for (int kc = 0; kc < 4; kc++) {
            float2 a[4];
#pragma unroll
            for (int k4 = 0; k4 < 4; k4++)
                a[k4] = *reinterpret_cast<const float2*>(Aq + (size_t)k4 * 8 * K + k0 + kc * 8);
            uint32_t Af[2][4];   // rna-round A (removes truncation bias)
            Af[0][0] = __float_as_uint(tf32r(a[0].x)); Af[0][1] = __float_as_uint(tf32r(a[1].x));
            Af[0][2] = __float_as_uint(tf32r(a[0].y)); Af[0][3] = __float_as_uint(tf32r(a[1].y));
            Af[1][0] = __float_as_uint(tf32r(a[2].x)); Af[1][1] = __float_as_uint(tf32r(a[3].x));
            Af[1][2] = __float_as_uint(tf32r(a[2].y)); Af[1][3] = __float_as_uint(tf32r(a[3].y));
            const float* bp0 = bs + (kc * 8 + 2 * q) * 68 + g;
            const float* bp1 = bp0 + 68;
#pragma unroll
            for (int nbk = 0; nbk < 8; nbk++) {
                uint32_t b0 = __float_as_uint(bp0[nbk * 8]);
                uint32_t b1 = __float_as_uint(bp1[nbk * 8]);
                mma_tf32(acc[0][nbk], Af[0][0], Af[0][1], Af[0][2], Af[0][3], b0, b1);
                mma_tf32(acc[1][nbk], Af[1][0], Af[1][1], Af[1][2], Af[1][3], b0, b1);
            }
        }
    }

    if (bias) {
#pragma unroll
        for (int nbk = 0; nbk < 8; nbk++) {
            float bv0 = bias[n0 + nbk * 8 + 2 * q];
            float bv1 = bias[n0 + nbk * 8 + 2 * q + 1];
#pragma unroll
            for (int x = 0; x < 2; x++) {
                acc[x][nbk][0] += bv0; acc[x][nbk][1] += bv1;
                acc[x][nbk][2] += bv0; acc[x][nbk][3] += bv1;
            }
        }
    }

    const float* gas = ga + (size_t)hh * 2 * HD;
    float as0[8], as1[8], ad0[8], ad1[8];
#pragma unroll
    for (int nbk = 0; nbk < 8; nbk++) {
        int col = nbk * 8 + 2 * q;
        as0[nbk] = gas[col];      as1[nbk] = gas[col + 1];
        ad0[nbk] = gas[HD + col]; ad1[nbk] = gas[HD + col + 1];
    }
#pragma unroll
    for (int x = 0; x < 2; x++) {
        int rA = m0 + wid * 32 + x * 16 + g;
        int rB = rA + 8;
        float psA = 0.f, pdA = 0.f, psB = 0.f, pdB = 0.f;
#pragma unroll
        for (int nbk = 0; nbk < 8; nbk++) {
            psA += acc[x][nbk][0] * as0[nbk] + acc[x][nbk][1] * as1[nbk];
            pdA += acc[x][nbk][0] * ad0[nbk] + acc[x][nbk][1] * ad1[nbk];
            psB += acc[x][nbk][2] * as0[nbk] + acc[x][nbk][3] * as1[nbk];
            pdB += acc[x][nbk][2] * ad0[nbk] + acc[x][nbk][3] * ad1[nbk];
        }
#pragma unroll
        for (int s = 1; s < 4; s <<= 1) {
            psA += __shfl_xor_sync(0xffffffffu, psA, s);
            pdA += __shfl_xor_sync(0xffffffffu, pdA, s);
            psB += __shfl_xor_sync(0xffffffffu, psB, s);
            pdB += __shfl_xor_sync(0xffffffffu, pdB, s);
        }
        if (q == 0) {
            int bbA = rA >> 10, nA = rA & (NT - 1);
            int bbB = rB >> 10, nB = rB & (NT - 1);
            esrc[((size_t)bbA * NH + hh) * NT + nA] = psA;
            edst[((size_t)bbA * NH + hh) * NT + nA] = pdA;
            esrc[((size_t)bbB * NH + hh) * NT + nB] = psB;
            edst[((size_t)bbB * NH + hh) * NT + nB] = pdB;
        }
        __half* cA = C + (size_t)rA * HID + n0 + 2 * q;
        __half* cB = C + (size_t)rB * HID + n0 + 2 * q;
#pragma unroll
        for (int nbk = 0; nbk < 8; nbk++) {
            *reinterpret_cast<uint32_t*>(cA + nbk * 8) = f2h2(acc[x][nbk][0], acc[x][nbk][1]);
            *reinterpret_cast<uint32_t*>(cB + nbk * 8) = f2h2(acc[x][nbk][2], acc[x][nbk][3]);
        }
    }
}

// ---------------- fp16 mma fused GAT attention, lane-contiguous j-permutation ----------------
// CTA = (head, batch, 128-row i-block), 128 threads (4 warps x 32 rows).
// __launch_bounds__(128,4): cap regs at 128 -> 4 CTAs/SM -> single 512-CTA wave.
__global__ void __launch_bounds__(128, 4) k_attn(
    const __half* __restrict__ gh, const float* __restrict__ esrc,
    const float* __restrict__ edst, const __half* __restrict__ twm,
    float* __restrict__ nodeout, int nb) {
    __shared__ __half hs[2][32 * 72];
    __shared__ __align__(16) __half edst_s[1024];
    __shared__ float red_s[4];

    int t = threadIdx.x;
    int wid = t >> 5, lid = t & 31;
    int hh = blockIdx.x & 7;
    int rem = blockIdx.x >> 3;
    int b = rem & 7;
    int iblk = rem >> 3;
    int i0 = iblk * 128;
    int bh = (nb == 1) ? 0 : b;

    float tmax = __uint_as_float(g_tmax_u);
    float s = __expf(-0.1f * tmax);

    const __half* hb = gh + (size_t)bh * NT * HID + hh * HD;
    int hrow = t >> 2;
    // permuted source j (within 32-tile) for this staging row
    int rr = hrow & 15, ch = hrow >> 4;
    int srcoff = 8 * ((rr & 7) >> 1) + 2 * ((rr >> 3) & 1) + (rr & 1) + 4 * ch;
    uint32_t hs_base = smem_u32(hs);
    uint32_t hdst = (uint32_t)hrow * 144u + (uint32_t)(t & 3) * 32u;

    // prologue: H tile 0 -> buf 0 (permuted)
    {
        const __half* src = hb + (size_t)srcoff * HID + (t & 3) * 16;
        cp16(hs_base + hdst, src);
        cp16(hs_base + hdst + 16u, src + 8);
        cp_commit();
    }

    // edst -> smem (scaled fp16); max over UNSCALED fp32
    const float* ed = edst + (size_t)(bh * NH + hh) * NT;
    float vmax = -1e30f;
#pragma unroll
    for (int u = 0; u < 8; u++) {
        float v = ed[t + u * 128];
        edst_s[t + u * 128] = __float2half_rn(v * s);
        vmax = fmaxf(vmax, v);
    }
#pragma unroll
    for (int ss = 16; ss; ss >>= 1) vmax = fmaxf(vmax, __shfl_xor_sync(0xffffffffu, vmax, ss));
    if (lid == 0) red_s[wid] = vmax;
    __syncthreads();
    float edmax = fmaxf(fmaxf(red_s[0], red_s[1]), fmaxf(red_s[2], red_s[3]));

    int g = lid >> 2, q = lid & 3;
    int rbase = wid * 32 + g;
    const float* esp = esrc + (size_t)(bh * NH + hh) * NT + i0;
    __half2 es2[4], m2n[4];
#pragma unroll
    for (int k = 0; k < 4; k++) {
        float esu = esp[rbase + k * 8];
        float m = fmaxf((esu + edmax) * LOG2E, 0.f);
        es2[k] = __float2half2_rn(esu * s);
        m2n[k] = __float2half2_rn(-m);
    }
    const __half2 c02   = __float2half2_rn(0.2f);
    const __half2 zero2 = __float2half2_rn(0.f);
    const uint32_t ONES = 0x3C003C00u;   // half2 {1,1}

    float acc[2][8][4] = {};
    float accl[2][4] = {};               // l via ones-MMA (fp32, exact k-reduction)
    // per-thread tw base: row (i0+rbase), j offset 8q halves
    const __half* twq = twm + ((size_t)(b * NT + i0 + rbase)) * NT + 8 * q;

    uint32_t lrow = (uint32_t)(((lid >> 3) & 1) * 8 + (lid & 7));
    uint32_t lcol = (uint32_t)((lid >> 4) * 8);
    uint32_t ldmoff = lrow * 144u + lcol * 2u;

    for (int T = 0; T < 32; T++) {
        int j0 = T * 32;
        cp_wait0();
        __syncthreads();
        if (T < 31) {
            uint32_t buf = (uint32_t)((T + 1) & 1) * (32u * 144u);
            const __half* src = hb + (size_t)(j0 + 32 + srcoff) * HID + (t & 3) * 16;
            cp16(hs_base + buf + hdst, src);
            cp16(hs_base + buf + hdst + 16u, src + 8);
            cp_commit();
        }
        uint32_t tilebase = hs_base + (uint32_t)(T & 1) * (32u * 144u) + ldmoff;

        // tw: one LDG.128 per k4-row (8 halves = lane's whole j-block)
        float4 twr[4];
#pragma unroll
        for (int k4 = 0; k4 < 4; k4++)
            twr[k4] = *reinterpret_cast<const float4*>(twq + (size_t)k4 * 8 * NT + j0);
        // ed: lane's j-block once per tile
        float4 edr = *reinterpret_cast<const float4*>(edst_s + j0 + 8 * q);
        const __half2* edv = reinterpret_cast<const __half2*>(&edr);

#pragma unroll
        for (int kt = 0; kt < 2; kt++) {
            uint32_t Bf[8][2];
#pragma unroll
            for (int m4 = 0; m4 < 4; m4++) {
                uint32_t addr = tilebase + (uint32_t)(kt * 16 * 144) + (uint32_t)(m4 * 16 * 2);
                ldm4t(Bf[m4 * 2][0], Bf[m4 * 2][1], Bf[m4 * 2 + 1][0], Bf[m4 * 2 + 1][1], addr);
            }
            __half2 ed2a = edv[2 * kt], ed2b = edv[2 * kt + 1];
            uint32_t Pa[4][2];
#pragma unroll
            for (int k4 = 0; k4 < 4; k4++) {
                const __half2* twv = reinterpret_cast<const __half2*>(&twr[k4]);
                __half2 twa = twv[2 * kt], twb = twv[2 * kt + 1];
                __half2 xx = __hadd2(es2[k4], ed2a);
                __half2 lk = __hmax2(xx, __hmul2(xx, c02));
                __half2 p2 = __hmul2(h2exp2(__hfma2(lk, twa, m2n[k4])), __hgt2(twa, zero2));
                Pa[k4][0] = *reinterpret_cast<uint32_t*>(&p2);
                xx = __hadd2(es2[k4], ed2b);
                lk = __hmax2(xx, __hmul2(xx, c02));
                __half2 p2b = __hmul2(h2exp2(__hfma2(lk, twb, m2n[k4])), __hgt2(twb, zero2));
                Pa[k4][1] = *reinterpret_cast<uint32_t*>(&p2b);
            }
#pragma unroll
            for (int x = 0; x < 2; x++) {
                uint32_t a0 = Pa[2 * x][0], a1 = Pa[2 * x + 1][0];
                uint32_t a2 = Pa[2 * x][1], a3 = Pa[2 * x + 1][1];
#pragma unroll
                for (int nbk = 0; nbk < 8; nbk++)
                    mma_f16(acc[x][nbk], a0, a1, a2, a3, Bf[nbk][0], Bf[nbk][1]);
                mma_f16(accl[x], a0, a1, a2, a3, ONES, ONES);   // row sums -> l
            }
        }
    }

    // epilogue: elu(acc/l); accl[x][0] = l(rowA), accl[x][2] = l(rowB)
#pragma unroll
    for (int x = 0; x < 2; x++) {
        int rA = wid * 32 + x * 16 + g;
        float* oA = nodeout + ((size_t)b * NT + i0 + rA) * HID + hh * HD + 2 * q;
        float* oB = oA + (size_t)8 * HID;
        float iA = 1.f / accl[x][0], iB = 1.f / accl[x][2];
#pragma unroll
        for (int nbk = 0; nbk < 8; nbk++) {
            float v0 = acc[x][nbk][0] * iA, v1 = acc[x][nbk][1] * iA;
            float v2 = acc[x][nbk][2] * iB, v3 = acc[x][nbk][3] * iB;
            float2 w0, w1;
            w0.x = v0 > 0.f ? v0 : (__expf(v0) - 1.f);
            w0.y = v1 > 0.f ? v1 : (__expf(v1) - 1.f);
            w1.x = v2 > 0.f ? v2 : (__expf(v2) - 1.f);
            w1.y = v3 > 0.f ? v3 : (__expf(v3) - 1.f);
            *reinterpret_cast<float2*>(oA + nbk * 8) = w0;
            *reinterpret_cast<float2*>(oB + nbk * 8) = w1;
        }
    }
}

// ---------------- final MLP ----------------
__global__ void k_final(const float* __restrict__ node, const int* __restrict__ topic_ids,
                        const float* __restrict__ attractiveness,
                        const float* __restrict__ aW, const float* __restrict__ ab,
                        const float* __restrict__ f1W, const float* __restrict__ f1b,
                        const float* __restrict__ f2W, const float* __restrict__ f2b,
                        float* __restrict__ out) {
    int b = blockIdx.x;
    int t = threadIdx.x;  // 512
    __shared__ float comb[HID];
    __shared__ float red[16];
    int tid = topic_ids[b];
    float av = attractiveness[b];
    comb[t] = node[((size_t)b * NT + tid) * HID + t] + av * aW[t] + ab[t];
    __syncthreads();
    float acc = f1b[t];
    const float4* w = reinterpret_cast<const float4*>(f1W + (size_t)t * HID);
    const float4* c4 = reinterpret_cast<const float4*>(comb);
#pragma unroll 8
    for (int o = 0; o < HID / 4; o++) {
        float4 wv = w[o], cv = c4[o];
        acc += wv.x * cv.x + wv.y * cv.y + wv.z * cv.z + wv.w * cv.w;
    }
    acc = fmaxf(acc, 0.f);
    float p = acc * f2W[t];
#pragma unroll
    for (int s = 16; s; s >>= 1) p += __shfl_xor_sync(0xffffffffu, p, s);
    if ((t & 31) == 0) red[t >> 5] = p;
    __syncthreads();
    if (t < 16) {
        float v = red[t];
#pragma unroll
        for (int s = 8; s; s >>= 1) v += __shfl_xor_sync(0xffffu, v, s);
        if (t == 0) out[b] = v + f2b[0];
    }
}

// ---------------- launch ----------------
extern "C" void kernel_launch(void* const* d_in, const int* in_sizes, int n_in,
                              void* d_out, int out_size) {
    const int*   topic_ids = (const int*)d_in[0];
    const int*   adj       = (const int*)d_in[1];
    const float* timem     = (const float*)d_in[2];
    const float* attract   = (const float*)d_in[3];
    const float* emb       = (const float*)d_in[4];
    const float* sW        = (const float*)d_in[5];
    const float* sb        = (const float*)d_in[6];
    const float* aW        = (const float*)d_in[7];
    const float* ab        = (const float*)d_in[8];
    const float* gW        = (const float*)d_in[9];
    const float* ga        = (const float*)d_in[10];
    const float* f1W       = (const float*)d_in[11];
    const float* f1b       = (const float*)d_in[12];
    const float* f2W       = (const float*)d_in[13];
    const float* f2b       = (const float*)d_in[14];
    float* out = (float*)d_out;

    void *pv;
    cudaGetSymbolAddress(&pv, g_twm);  __half* twm = (__half*)pv;
    cudaGetSymbolAddress(&pv, g_weff); float* weff = (float*)pv;
    cudaGetSymbolAddress(&pv, g_beff); float* beff = (float*)pv;
    cudaGetSymbolAddress(&pv, g_h);    __half* h   = (__half*)pv;
    cudaGetSymbolAddress(&pv, g_node); float* node = (float*)pv;
    cudaGetSymbolAddress(&pv, g_esrc); float* esrc = (float*)pv;
    cudaGetSymbolAddress(&pv, g_edst); float* edst = (float*)pv;

    int n4 = (BATCH * NT * NT) / 4;

    // 1: twm fp16, polynomial exp (+ tmax)
    k_twm<<<4096, 256>>>(reinterpret_cast<const float4*>(timem),
                         reinterpret_cast<const int4*>(adj), n4);
    // 2: Weff/beff
    k_weff<<<dim3(TD / 64, HID / 64), 256>>>(sW, sb, gW, weff, beff);
    // 3: h0 = emb @ Weff + beff (HMMA), fused esrc/edst, h -> fp16
    k_gmma<<<dim3(NT / 128, NH), 128>>>(emb, weff, h, beff, TD, 0, ga, esrc, edst);
    // 4: attention layer 0  (<- ncu capture slot)
    k_attn<<<BATCH * NH * (NT / 128), 128>>>(h, esrc, edst, twm, node, 1);
    // 5: h1 = node @ W1cat (HMMA), fused esrc/edst, h -> fp16
    k_gmma<<<dim3(BATCH * NT / 128, NH), 128>>>(node, gW + (size_t)NH * HID * HD, h,
                                                nullptr, HID, 1, ga + (size_t)NH * 2 * HD,
                                                esrc, edst);
    // 6: attention layer 1
    k_attn<<<BATCH * NH * (NT / 128), 128>>>(h, esrc, edst, twm, node, BATCH);
    // 7: final MLP
    k_final<<<BATCH, 512>>>(node, topic_ids, attract, aW, ab, f1W, f1b, f2W, f2b, out);
}

// round 16
// speedup vs baseline: 1.2837x; 1.2837x over previous
#include <cuda_runtime.h>
#include <cuda_fp16.h>
#include <math.h>
#include <stddef.h>
#include <stdint.h>

#define BATCH 8
#define NT 1024
#define TD 128
#define HID 512
#define NH 8
#define HD 64
#define LOG2E 1.4426950408889634f

// ---------------- helpers ----------------
__device__ __forceinline__ void mma_f16(float* c,
    uint32_t a0, uint32_t a1, uint32_t a2, uint32_t a3,
    uint32_t b0, uint32_t b1){
    asm("mma.sync.aligned.m16n8k16.row.col.f32.f16.f16.f32 "
        "{%0,%1,%2,%3}, {%4,%5,%6,%7}, {%8,%9}, {%0,%1,%2,%3};"
        : "+f"(c[0]), "+f"(c[1]), "+f"(c[2]), "+f"(c[3])
        : "r"(a0), "r"(a1), "r"(a2), "r"(a3), "r"(b0), "r"(b1));
}
__device__ __forceinline__ void ldm4t(uint32_t& r0, uint32_t& r1, uint32_t& r2, uint32_t& r3,
                                      uint32_t addr){
    asm volatile("ldmatrix.sync.aligned.m8n8.x4.trans.shared.b16 {%0,%1,%2,%3}, [%4];"
                 : "=r"(r0), "=r"(r1), "=r"(r2), "=r"(r3) : "r"(addr));
}
__device__ __forceinline__ void ldm4(uint32_t& r0, uint32_t& r1, uint32_t& r2, uint32_t& r3,
                                     uint32_t addr){
    asm volatile("ldmatrix.sync.aligned.m8n8.x4.shared.b16 {%0,%1,%2,%3}, [%4];"
                 : "=r"(r0), "=r"(r1), "=r"(r2), "=r"(r3) : "r"(addr));
}
__device__ __forceinline__ uint32_t smem_u32(const void* p){
    uint32_t a;
    asm("{ .reg .u64 t; cvta.to.shared.u64 t, %1; cvt.u32.u64 %0, t; }" : "=r"(a) : "l"(p));
    return a;
}
__device__ __forceinline__ void cp16(uint32_t dst, const void* src){
    asm volatile("cp.async.cg.shared.global [%0], [%1], 16;" :: "r"(dst), "l"(src));
}
__device__ __forceinline__ void cp_commit(){
    asm volatile("cp.async.commit_group;" ::: "memory");
}
__device__ __forceinline__ void cp_wait0(){
    asm volatile("cp.async.wait_group 0;" ::: "memory");
}
__device__ __forceinline__ uint32_t f2h2(float lo, float hi){
    __half2 h = __floats2half2_rn(lo, hi);
    return *reinterpret_cast<uint32_t*>(&h);
}
// exp(0.1*t)*log2e for t in [0,1]: cubic Taylor in x=0.1t, rel err < 5e-6 (<< fp16 ulp)
__device__ __forceinline__ float expw(float t){
    float x = 0.1f * t;
    float p = fmaf(x, 0.16666667f, 0.5f);
    p = fmaf(x, p, 1.f);
    p = fmaf(x, p, 1.f);
    return p * LOG2E;
}

// ---------------- device scratch (static; no allocation) ----------------
__device__ unsigned g_tmax_u;                 // zero at load; atomicMax idempotent across replays
__device__ __half g_twm[BATCH * NT * NT];     // adj ? exp(0.1*t)*log2e : -1  (fp16)
__device__ __half g_embh[NT * TD];            // emb fp16
__device__ __half g_w1h[NH * HID * HD];       // gat_W[1] fp16
__device__ __half g_weffh[TD * HID];          // struct_W^T @ W0cat (fp16)
__device__ float g_beff[HID];                 // struct_b @ W0cat
__device__ __half g_h[BATCH * NT * HID];      // h (fp16, rn)
__device__ __half g_nodeh[BATCH * NT * HID];  // layer-0 node (fp16, feeds gmma1)
__device__ float g_node[BATCH * NT * HID];    // layer-1 node (fp32, feeds k_final)
__device__ float g_esrc[BATCH * NH * NT];
__device__ float g_edst[BATCH * NH * NT];

// ---------------- fp32 -> fp16 conversions (emb + gat_W[1]) ----------------
__global__ void k_cvt(const float* __restrict__ emb, const float* __restrict__ gW1) {
    int i = blockIdx.x * 256 + threadIdx.x;       // < 262144
    if (i < NT * TD) g_embh[i] = __float2half_rn(emb[i]);
    g_w1h[i] = __float2half_rn(gW1[i]);
}

// ---------------- twm (fp16, polynomial exp) + tmax fused ----------------
__global__ void k_twm(const float4* __restrict__ tm, const int4* __restrict__ adj, int n4) {
    float m = 0.f;
    int stride = gridDim.x * blockDim.x;
    __half2* outp = reinterpret_cast<__half2*>(g_twm);
    for (int i = blockIdx.x * blockDim.x + threadIdx.x; i < n4; i += stride) {
        float4 t = tm[i];
        int4 a = adj[i];
        float4 o;
        o.x = a.x ? expw(t.x) : -1.f;
        o.y = a.y ? expw(t.y) : -1.f;
        o.z = a.z ? expw(t.z) : -1.f;
        o.w = a.w ? expw(t.w) : -1.f;
        outp[i * 2 + 0] = __floats2half2_rn(o.x, o.y);
        outp[i * 2 + 1] = __floats2half2_rn(o.z, o.w);
        m = fmaxf(m, fmaxf(fmaxf(t.x, t.y), fmaxf(t.z, t.w)));
    }
#pragma unroll
    for (int s = 16; s; s >>= 1) m = fmaxf(m, __shfl_xor_sync(0xffffffffu, m, s));
    __shared__ float sm[8];
    if ((threadIdx.x & 31) == 0) sm[threadIdx.x >> 5] = m;
    __syncthreads();
    if (threadIdx.x == 0) {
        for (int w = 1; w < 8; w++) m = fmaxf(m, sm[w]);
        atomicMax(&g_tmax_u, __float_as_uint(m));   // t >= 0: uint order == float order
    }
}

// ---------------- Weff = struct_W^T @ W0cat (fp16 out); beff = struct_b @ W0cat ----------------
__global__ void k_weff(const float* __restrict__ sW, const float* __restrict__ sb,
                       const float* __restrict__ gW0,
                       __half* __restrict__ weffh, float* __restrict__ beff) {
    __shared__ float As[32][68];
    __shared__ float Bs[32][68];
    int t = threadIdx.x;
    int tx = t & 15, ty = t >> 4;
    int m0 = blockIdx.x * 64, n0 = blockIdx.y * 64;
    int hh = n0 >> 6;
    const float* B0 = gW0 + (size_t)hh * (HID * HD);
    float acc[4][4] = {};
    int bk = t >> 3, bnc = (t & 7) * 8;

    for (int kt = 0; kt < HID; kt += 32) {
        {
            const float* ap = sW + (size_t)(kt + bk) * TD + m0 + bnc;
            *reinterpret_cast<float4*>(&As[bk][bnc])     = *reinterpret_cast<const float4*>(ap);
            *reinterpret_cast<float4*>(&As[bk][bnc + 4]) = *reinterpret_cast<const float4*>(ap + 4);
            const float* bp = B0 + (size_t)(kt + bk) * HD + bnc;
            *reinterpret_cast<float4*>(&Bs[bk][bnc])     = *reinterpret_cast<const float4*>(bp);
            *reinterpret_cast<float4*>(&Bs[bk][bnc + 4]) = *reinterpret_cast<const float4*>(bp + 4);
        }
        __syncthreads();
#pragma unroll
        for (int k = 0; k < 32; k++) {
            float4 a4 = *reinterpret_cast<const float4*>(&As[k][ty * 4]);
            float4 b4 = *reinterpret_cast<const float4*>(&Bs[k][tx * 4]);
            acc[0][0] += a4.x * b4.x; acc[0][1] += a4.x * b4.y; acc[0][2] += a4.x * b4.z; acc[0][3] += a4.x * b4.w;
            acc[1][0] += a4.y * b4.x; acc[1][1] += a4.y * b4.y; acc[1][2] += a4.y * b4.z; acc[1][3] += a4.y * b4.w;
            acc[2][0] += a4.z * b4.x; acc[2][1] += a4.z * b4.y; acc[2][2] += a4.z * b4.z; acc[2][3] += a4.z * b4.w;
            acc[3][0] += a4.w * b4.x; acc[3][1] += a4.w * b4.y; acc[3][2] += a4.w * b4.z; acc[3][3] += a4.w * b4.w;
        }
        __syncthreads();
    }
#pragma unroll
    for (int ii = 0; ii < 4; ii++) {
        uint32_t lo = f2h2(acc[ii][0], acc[ii][1]);
        uint32_t hi = f2h2(acc[ii][2], acc[ii][3]);
        *reinterpret_cast<uint2*>(weffh + (size_t)(m0 + ty * 4 + ii) * HID + n0 + tx * 4) =
            make_uint2(lo, hi);
    }
    if (blockIdx.x == 0 && t < 64) {
        float s = 0.f;
        for (int k = 0; k < HID; k++) s += sb[k] * B0[(size_t)k * HD + t];
        beff[n0 + t] = s;
    }
}

// ---------------- fp16 HMMA GEMM (M-block 128, N=64=one head) + fused se; h out fp16 ----------------
// A fp16 [M,K] row-major; bgat=0: B rows stride HID at col n0; bgat=1: B slab stride HD.
// A tile 128x32 staged stride-40 (ldmatrix x4 non-trans), B tile 32x64 stride-72 (x4 trans).
__global__ void __launch_bounds__(128) k_gmma(
    const __half* __restrict__ A, const __half* __restrict__ B,
    __half* __restrict__ C, const float* __restrict__ bias,
    int K, int bgat, const float* __restrict__ ga,
    float* __restrict__ esrc, float* __restrict__ edst) {
    __shared__ __half As[2][128 * 40];
    __shared__ __half Bs2[2][32 * 72];

    int t = threadIdx.x;
    int wid = t >> 5, lid = t & 31;
    int g = lid >> 2, q = lid & 3;
    int m0 = blockIdx.x * 128;
    int hh = blockIdx.y;
    int n0 = hh * 64;

    const __half* Bsrc = bgat ? (B + (size_t)hh * (HID * HD)) : (B + n0);
    int bstride = bgat ? HD : HID;

    uint32_t as_base = smem_u32(As);
    uint32_t bs_base = smem_u32(Bs2);
    uint32_t adst = (uint32_t)t * 80u;                        // A: row t, 4x cp16
    uint32_t bdst = (uint32_t)(t >> 2) * 144u + (uint32_t)(t & 3) * 32u;  // B: 2x cp16

    // prologue: tile 0
    {
        const __half* asrc = A + (size_t)(m0 + t) * K;
#pragma unroll
        for (int c = 0; c < 4; c++) cp16(as_base + adst + c * 16u, asrc + c * 8);
        const __half* bsrc = Bsrc + (size_t)(t >> 2) * bstride + (t & 3) * 16;
        cp16(bs_base + bdst, bsrc);
        cp16(bs_base + bdst + 16u, bsrc + 8);
        cp_commit();
    }

    // ldmatrix lane offsets
    uint32_t a_lrow = (uint32_t)(lid & 15);
    uint32_t a_lcol = (uint32_t)((lid >> 4) * 8);
    uint32_t b_lrow = (uint32_t)(((lid >> 3) & 1) * 8 + (lid & 7));
    uint32_t b_lcol = (uint32_t)((lid >> 4) * 8);
    uint32_t bldmoff = b_lrow * 144u + b_lcol * 2u;

    float acc[2][8][4] = {};
    int ntiles = K / 32;

    for (int T = 0; T < ntiles; T++) {
        int k0 = T * 32;
        cp_wait0();
        __syncthreads();
        if (T + 1 < ntiles) {
            uint32_t abuf = (uint32_t)((T + 1) & 1) * (128u * 80u);
            uint32_t bbuf = (uint32_t)((T + 1) & 1) * (32u * 144u);
            const __half* asrc = A + (size_t)(m0 + t) * K + k0 + 32;
#pragma unroll
            for (int c = 0; c < 4; c++) cp16(as_base + abuf + adst + c * 16u, asrc + c * 8);
            const __half* bsrc = Bsrc + (size_t)(k0 + 32 + (t >> 2)) * bstride + (t & 3) * 16;
            cp16(bs_base + bbuf + bdst, bsrc);
            cp16(bs_base + bbuf + bdst + 16u, bsrc + 8);
            cp_commit();
        }
        uint32_t acur = as_base + (uint32_t)(T & 1) * (128u * 80u);
        uint32_t bcur = bs_base + (uint32_t)(T & 1) * (32u * 144u) + bldmoff;

#pragma unroll
        for (int kt = 0; kt < 2; kt++) {
            uint32_t Bf[8][2];
#pragma unroll
            for (int m4 = 0; m4 < 4; m4++) {
                uint32_t addr = bcur + (uint32_t)(kt * 16 * 144) + (uint32_t)(m4 * 16 * 2);
                ldm4t(Bf[m4 * 2][0], Bf[m4 * 2][1], Bf[m4 * 2 + 1][0], Bf[m4 * 2 + 1][1], addr);
            }
#pragma unroll
            for (int x = 0; x < 2; x++) {
                uint32_t Aa0, Aa1, Aa2, Aa3;
                uint32_t addr = acur + (uint32_t)(wid * 32 + x * 16 + a_lrow) * 80u
                              + (a_lcol + (uint32_t)(kt * 16)) * 2u;
                ldm4(Aa0, Aa1, Aa2, Aa3, addr);
#pragma unroll
                for (int nbk = 0; nbk < 8; nbk++)
                    mma_f16(acc[x][nbk], Aa0, Aa1, Aa2, Aa3, Bf[nbk][0], Bf[nbk][1]);
            }
        }
    }

    if (bias) {
#pragma unroll
        for (int nbk = 0; nbk < 8; nbk++) {
            float bv0 = bias[n0 + nbk * 8 + 2 * q];
            float bv1 = bias[n0 + nbk * 8 + 2 * q + 1];
#pragma unroll
            for (int x = 0; x < 2; x++) {
                acc[x][nbk][0] += bv0; acc[x][nbk][1] += bv1;
                acc[x][nbk][2] += bv0; acc[x][nbk][3] += bv1;
            }
        }
    }

    const float* gas = ga + (size_t)hh * 2 * HD;
    float as0[8], as1[8], ad0[8], ad1[8];
#pragma unroll
    for (int nbk = 0; nbk < 8; nbk++) {
        int col = nbk * 8 + 2 * q;
        as0[nbk] = gas[col];      as1[nbk] = gas[col + 1];
        ad0[nbk] = gas[HD + col]; ad1[nbk] = gas[HD + col + 1];
    }
#pragma unroll
    for (int x = 0; x < 2; x++) {
        int rA = m0 + wid * 32 + x * 16 + g;
        int rB = rA + 8;
        float psA = 0.f, pdA = 0.f, psB = 0.f, pdB = 0.f;
#pragma unroll
        for (int nbk = 0; nbk < 8; nbk++) {
            psA += acc[x][nbk][0] * as0[nbk] + acc[x][nbk][1] * as1[nbk];
            pdA += acc[x][nbk][0] * ad0[nbk] + acc[x][nbk][1] * ad1[nbk];
            psB += acc[x][nbk][2] * as0[nbk] + acc[x][nbk][3] * as1[nbk];
            pdB += acc[x][nbk][2] * ad0[nbk] + acc[x][nbk][3] * ad1[nbk];
        }
#pragma unroll
        for (int s = 1; s < 4; s <<= 1) {
            psA += __shfl_xor_sync(0xffffffffu, psA, s);
            pdA += __shfl_xor_sync(0xffffffffu, pdA, s);
            psB += __shfl_xor_sync(0xffffffffu, psB, s);
            pdB += __shfl_xor_sync(0xffffffffu, pdB, s);
        }
        if (q == 0) {
            int bbA = rA >> 10, nA = rA & (NT - 1);
            int bbB = rB >> 10, nB = rB & (NT - 1);
            esrc[((size_t)bbA * NH + hh) * NT + nA] = psA;
            edst[((size_t)bbA * NH + hh) * NT + nA] = pdA;
            esrc[((size_t)bbB * NH + hh) * NT + nB] = psB;
            edst[((size_t)bbB * NH + hh) * NT + nB] = pdB;
        }
        __half* cA = C + (size_t)rA * HID + n0 + 2 * q;
        __half* cB = C + (size_t)rB * HID + n0 + 2 * q;
#pragma unroll
        for (int nbk = 0; nbk < 8; nbk++) {
            *reinterpret_cast<uint32_t*>(cA + nbk * 8) = f2h2(acc[x][nbk][0], acc[x][nbk][1]);
            *reinterpret_cast<uint32_t*>(cB + nbk * 8) = f2h2(acc[x][nbk][2], acc[x][nbk][3]);
        }
    }
}

// ---------------- fp16 mma fused GAT attention (round-13 core, dual-dtype output) ----------------
// CTA = (head, batch, 128-row i-block), 128 threads (4 warps x 32 rows).
__global__ void __launch_bounds__(128) k_attn(
    const __half* __restrict__ gh, const float* __restrict__ esrc,
    const float* __restrict__ edst, const __half* __restrict__ twm,
    float* __restrict__ nodef, __half* __restrict__ nodeh, int nb) {
    __shared__ __half hs[2][32 * 72];
    __shared__ __half edst_s[1024];
    __shared__ float red_s[4];

    int t = threadIdx.x;
    int wid = t >> 5, lid = t & 31;
    int hh = blockIdx.x & 7;
    int rem = blockIdx.x >> 3;
    int b = rem & 7;
    int iblk = rem >> 3;
    int i0 = iblk * 128;
    int bh = (nb == 1) ? 0 : b;

    float tmax = __uint_as_float(g_tmax_u);
    float s = __expf(-0.1f * tmax);

    const __half* hb = gh + (size_t)bh * NT * HID + hh * HD;
    int hrow = t >> 2;
    uint32_t hs_base = smem_u32(hs);
    uint32_t hdst = (uint32_t)hrow * 144u + (uint32_t)(t & 3) * 32u;

    // prologue: H tile 0 -> buf 0
    {
        const __half* src = hb + (size_t)hrow * HID + (t & 3) * 16;
        cp16(hs_base + hdst, src);
        cp16(hs_base + hdst + 16u, src + 8);
        cp_commit();
    }

    // edst -> smem (scaled fp16); max over UNSCALED fp32
    const float* ed = edst + (size_t)(bh * NH + hh) * NT;
    float vmax = -1e30f;
#pragma unroll
    for (int u = 0; u < 8; u++) {
        float v = ed[t + u * 128];
        edst_s[t + u * 128] = __float2half_rn(v * s);
        vmax = fmaxf(vmax, v);
    }
#pragma unroll
    for (int ss = 16; ss; ss >>= 1) vmax = fmaxf(vmax, __shfl_xor_sync(0xffffffffu, vmax, ss));
    if (lid == 0) red_s[wid] = vmax;
    __syncthreads();
    float edmax = fmaxf(fmaxf(red_s[0], red_s[1]), fmaxf(red_s[2], red_s[3]));

    int g = lid >> 2, q = lid & 3;
    int rbase = wid * 32 + g;
    const float* esp = esrc + (size_t)(bh * NH + hh) * NT + i0;
    __half2 es2[4], m2n[4];
#pragma unroll
    for (int k = 0; k < 4; k++) {
        float esu = esp[rbase + k * 8];
        float m = fmaxf((esu + edmax) * LOG2E, 0.f);
        es2[k] = __float2half2_rn(esu * s);
        m2n[k] = __float2half2_rn(-m);
    }
    const __half2 c02   = __float2half2_rn(0.2f);
    const __half2 zero2 = __float2half2_rn(0.f);
    const uint32_t ONES = 0x3C003C00u;   // half2 {1,1}

    float acc[2][8][4] = {};
    float accl[2][4] = {};               // l via ones-MMA (fp32, exact k-reduction)
    const __half* twq = twm + ((size_t)(b * NT + i0 + rbase)) * NT + 2 * q;

    uint32_t lrow = (uint32_t)(((lid >> 3) & 1) * 8 + (lid & 7));
    uint32_t lcol = (uint32_t)((lid >> 4) * 8);
    uint32_t ldmoff = lrow * 144u + lcol * 2u;

    for (int T = 0; T < 32; T++) {
        int j0 = T * 32;
        cp_wait0();
        __syncthreads();
        if (T < 31) {
            uint32_t buf = (uint32_t)((T + 1) & 1) * (32u * 144u);
            const __half* src = hb + (size_t)(j0 + 32 + hrow) * HID + (t & 3) * 16;
            cp16(hs_base + buf + hdst, src);
            cp16(hs_base + buf + hdst + 16u, src + 8);
            cp_commit();
        }
        uint32_t tilebase = hs_base + (uint32_t)(T & 1) * (32u * 144u) + ldmoff;

#pragma unroll
        for (int kt = 0; kt < 2; kt++) {
            int jb = j0 + kt * 16;
            uint32_t Bf[8][2];
#pragma unroll
            for (int m4 = 0; m4 < 4; m4++) {
                uint32_t addr = tilebase + (uint32_t)(kt * 16 * 144) + (uint32_t)(m4 * 16 * 2);
                ldm4t(Bf[m4 * 2][0], Bf[m4 * 2][1], Bf[m4 * 2 + 1][0], Bf[m4 * 2 + 1][1], addr);
            }
            __half2 ed2a = *reinterpret_cast<const __half2*>(edst_s + jb + 2 * q);
            __half2 ed2b = *reinterpret_cast<const __half2*>(edst_s + jb + 8 + 2 * q);
            uint32_t Pa[4][2];
#pragma unroll
            for (int k4 = 0; k4 < 4; k4++) {
                const __half* twp = twq + (size_t)k4 * 8 * NT + jb;
                __half2 twa = *reinterpret_cast<const __half2*>(twp);
                __half2 twb = *reinterpret_cast<const __half2*>(twp + 8);
                __half2 xx = __hadd2(es2[k4], ed2a);
                __half2 lk = __hmax2(xx, __hmul2(xx, c02));
                __half2 p2 = __hmul2(h2exp2(__hfma2(lk, twa, m2n[k4])), __hgt2(twa, zero2));
                Pa[k4][0] = *reinterpret_cast<uint32_t*>(&p2);
                xx = __hadd2(es2[k4], ed2b);
                lk = __hmax2(xx, __hmul2(xx, c02));
                __half2 p2b = __hmul2(h2exp2(__hfma2(lk, twb, m2n[k4])), __hgt2(twb, zero2));
                Pa[k4][1] = *reinterpret_cast<uint32_t*>(&p2b);
            }
#pragma unroll
            for (int x = 0; x < 2; x++) {
                uint32_t a0 = Pa[2 * x][0], a1 = Pa[2 * x + 1][0];
                uint32_t a2 = Pa[2 * x][1], a3 = Pa[2 * x + 1][1];
#pragma unroll
                for (int nbk = 0; nbk < 8; nbk++)
                    mma_f16(acc[x][nbk], a0, a1, a2, a3, Bf[nbk][0], Bf[nbk][1]);
                mma_f16(accl[x], a0, a1, a2, a3, ONES, ONES);   // row sums -> l
            }
        }
    }

    // epilogue: elu(acc/l); accl[x][0] = l(rowA), accl[x][2] = l(rowB)
#pragma unroll
    for (int x = 0; x < 2; x++) {
        int rA = wid * 32 + x * 16 + g;
        size_t offA = ((size_t)b * NT + i0 + rA) * HID + hh * HD + 2 * q;
        size_t offB = offA + (size_t)8 * HID;
        float iA = 1.f / accl[x][0], iB = 1.f / accl[x][2];
#pragma unroll
        for (int nbk = 0; nbk < 8; nbk++) {
            float v0 = acc[x][nbk][0] * iA, v1 = acc[x][nbk][1] * iA;
            float v2 = acc[x][nbk][2] * iB, v3 = acc[x][nbk][3] * iB;
            float w0 = v0 > 0.f ? v0 : (__expf(v0) - 1.f);
            float w1 = v1 > 0.f ? v1 : (__expf(v1) - 1.f);
            float w2 = v2 > 0.f ? v2 : (__expf(v2) - 1.f);
            float w3 = v3 > 0.f ? v3 : (__expf(v3) - 1.f);
            if (nodeh) {
                *reinterpret_cast<uint32_t*>(nodeh + offA + nbk * 8) = f2h2(w0, w1);
                *reinterpret_cast<uint32_t*>(nodeh + offB + nbk * 8) = f2h2(w2, w3);
            } else {
                *reinterpret_cast<float2*>(nodef + offA + nbk * 8) = make_float2(w0, w1);
                *reinterpret_cast<float2*>(nodef + offB + nbk * 8) = make_float2(w2, w3);
            }
        }
    }
}

// ---------------- final MLP ----------------
__global__ void k_final(const float* __restrict__ node, const int* __restrict__ topic_ids,
                        const float* __restrict__ attractiveness,
                        const float* __restrict__ aW, const float* __restrict__ ab,
                        const float* __restrict__ f1W, const float* __restrict__ f1b,
                        const float* __restrict__ f2W, const float* __restrict__ f2b,
                        float* __restrict__ out) {
    int b = blockIdx.x;
    int t = threadIdx.x;  // 512
    __shared__ float comb[HID];
    __shared__ float red[16];
    int tid = topic_ids[b];
    float av = attractiveness[b];
    comb[t] = node[((size_t)b * NT + tid) * HID + t] + av * aW[t] + ab[t];
    __syncthreads();
    float acc = f1b[t];
    const float4* w = reinterpret_cast<const float4*>(f1W + (size_t)t * HID);
    const float4* c4 = reinterpret_cast<const float4*>(comb);
#pragma unroll 8
    for (int o = 0; o < HID / 4; o++) {
        float4 wv = w[o], cv = c4[o];
        acc += wv.x * cv.x + wv.y * cv.y + wv.z * cv.z + wv.w * cv.w;
    }
    acc = fmaxf(acc, 0.f);
    float p = acc * f2W[t];
#pragma unroll
    for (int s = 16; s; s >>= 1) p += __shfl_xor_sync(0xffffffffu, p, s);
    if ((t & 31) == 0) red[t >> 5] = p;
    __syncthreads();
    if (t < 16) {
        float v = red[t];
#pragma unroll
        for (int s = 8; s; s >>= 1) v += __shfl_xor_sync(0xffffu, v, s);
        if (t == 0) out[b] = v + f2b[0];
    }
}

// ---------------- launch ----------------
extern "C" void kernel_launch(void* const* d_in, const int* in_sizes, int n_in,
                              void* d_out, int out_size) {
    const int*   topic_ids = (const int*)d_in[0];
    const int*   adj       = (const int*)d_in[1];
    const float* timem     = (const float*)d_in[2];
    const float* attract   = (const float*)d_in[3];
    const float* emb       = (const float*)d_in[4];
    const float* sW        = (const float*)d_in[5];
    const float* sb        = (const float*)d_in[6];
    const float* aW        = (const float*)d_in[7];
    const float* ab        = (const float*)d_in[8];
    const float* gW        = (const float*)d_in[9];
    const float* ga        = (const float*)d_in[10];
    const float* f1W       = (const float*)d_in[11];
    const float* f1b       = (const float*)d_in[12];
    const float* f2W       = (const float*)d_in[13];
    const float* f2b       = (const float*)d_in[14];
    float* out = (float*)d_out;

    void *pv;
    cudaGetSymbolAddress(&pv, g_twm);   __half* twm   = (__half*)pv;
    cudaGetSymbolAddress(&pv, g_embh);  __half* embh  = (__half*)pv;
    cudaGetSymbolAddress(&pv, g_w1h);   __half* w1h   = (__half*)pv;
    cudaGetSymbolAddress(&pv, g_weffh); __half* weffh = (__half*)pv;
    cudaGetSymbolAddress(&pv, g_beff);  float* beff   = (float*)pv;
    cudaGetSymbolAddress(&pv, g_h);     __half* h     = (__half*)pv;
    cudaGetSymbolAddress(&pv, g_nodeh); __half* nodeh = (__half*)pv;
    cudaGetSymbolAddress(&pv, g_node);  float* node   = (float*)pv;
    cudaGetSymbolAddress(&pv, g_esrc);  float* esrc   = (float*)pv;
    cudaGetSymbolAddress(&pv, g_edst);  float* edst   = (float*)pv;

    int n4 = (BATCH * NT * NT) / 4;

    // 1: fp16 conversions (emb, gat_W[1])
    k_cvt<<<(NH * HID * HD) / 256, 256>>>(emb, gW + (size_t)NH * HID * HD);
    // 2: twm fp16, polynomial exp (+ tmax)
    k_twm<<<4096, 256>>>(reinterpret_cast<const float4*>(timem),
                         reinterpret_cast<const int4*>(adj), n4);
    // 3: Weff (fp16) / beff
    k_weff<<<dim3(TD / 64, HID / 64), 256>>>(sW, sb, gW, weffh, beff);
    // 4: h0 = embh @ weffh + beff (fp16 MMA), fused esrc/edst  (<- ncu capture slot)
    k_gmma<<<dim3(NT / 128, NH), 128>>>(embh, weffh, h, beff, TD, 0, ga, esrc, edst);
    // 5: attention layer 0 -> node fp16
    k_attn<<<BATCH * NH * (NT / 128), 128>>>(h, esrc, edst, twm, nullptr, nodeh, 1);
    // 6: h1 = nodeh @ w1h (fp16 MMA), fused esrc/edst
    k_gmma<<<dim3(BATCH * NT / 128, NH), 128>>>(nodeh, w1h, h, nullptr, HID, 1,
                                                ga + (size_t)NH * 2 * HD, esrc, edst);
    // 7: attention layer 1 -> node fp32
    k_attn<<<BATCH * NH * (NT / 128), 128>>>(h, esrc, edst, twm, node, nullptr, BATCH);
    // 8: final MLP
    k_final<<<BATCH, 512>>>(node, topic_ids, attract, aW, ab, f1W, f1b, f2W, f2b, out);
}